// round 13
// baseline (speedup 1.0000x reference)
#include <cuda_runtime.h>

#define BB 8
#define PP 12000
#define NP (BB*PP)
#define XN_ 144
#define CELLS (144*144)
#define NC (BB*CELLS)
#define NBLK 304
#define NWARPS (NBLK*8)

// per-(batch,cell) winning pillar index (last write wins == max p)
__device__ int  g_winner[NC];
__device__ int  g_count;
__device__ int2 g_list[NP];      // (pillar id, b*CELLS + flat)
// dense per-cell features, channel-major: g_feat[(b*CELLS+cell)*64 + c]
__device__ float g_feat[(size_t)NC * 64];

__global__ void k_winner(const int* __restrict__ idx) {
    int i = blockIdx.x * blockDim.x + threadIdx.x;   // grid sized exactly NP
    int y = idx[i * 3 + 1];
    int x = idx[i * 3 + 2];
    x = min(max(x, 0), 143);
    y = min(max(y, 0), 143);
    int b = i / PP;
    int p = i - b * PP;
    atomicMax(&g_winner[b * CELLS + y * XN_ + x], p);
}

// Compact winners into g_list (warp-aggregated atomic: 1 atomicAdd per warp).
__global__ void k_collect(const int* __restrict__ idx) {
    int i = blockIdx.x * blockDim.x + threadIdx.x;
    int lane = threadIdx.x & 31;
    int y = idx[i * 3 + 1];
    int x = idx[i * 3 + 2];
    x = min(max(x, 0), 143);
    y = min(max(y, 0), 143);
    int b = i / PP;
    int p = i - b * PP;
    int cell = b * CELLS + y * XN_ + x;
    bool win = (g_winner[cell] == p);
    unsigned m = __ballot_sync(0xFFFFFFFFu, win);
    int base = 0;
    if (lane == 0 && m) base = atomicAdd(&g_count, __popc(m));
    base = __shfl_sync(0xFFFFFFFFu, base, 0);
    if (win) {
        int pos = base + __popc(m & ((1u << lane) - 1u));
        g_list[pos] = make_int2(i, cell);
    }
}

__device__ __forceinline__ unsigned long long fma2(unsigned long long a,
                                                   unsigned long long b,
                                                   unsigned long long c) {
    unsigned long long d;
    asm("fma.rn.f32x2 %0, %1, %2, %3;" : "=l"(d) : "l"(a), "l"(b), "l"(c));
    return d;
}
__device__ __forceinline__ unsigned long long pack2(float lo, float hi) {
    unsigned long long d;
    asm("mov.b64 %0, {%1, %2};" : "=l"(d) : "f"(lo), "f"(hi));
    return d;
}
__device__ __forceinline__ void unpack2(unsigned long long v, float& lo, float& hi) {
    asm("mov.b64 {%0, %1}, %2;" : "=f"(lo), "=f"(hi) : "l"(v));
}

// Persistent kernel over the compacted winner list. One warp per winner.
// Lane = (cg, mg): cg = lane>>2 owns channels [8cg, 8cg+8),
//                  mg = lane&3  owns m-points  [8mg, 8mg+8).
// Pillar x-values stored DUPLICATED in smem as (v,v) float2 so the inner loop
// is LDS.64 -> FFMA2 with zero splat MOVs. Double-buffered per warp; next
// pillar's 288 floats are register-staged (9/lane) during current compute.
// Output: dense channel-major g_feat (warp = 256 contiguous bytes).
__global__ void __launch_bounds__(256, 2) k_compute(
    const float* __restrict__ pillars,
    const float* __restrict__ cw,
    const float* __restrict__ gamma,
    const float* __restrict__ beta,
    const float* __restrict__ mean,
    const float* __restrict__ var)
{
    __shared__ __align__(16) float2 sm[8][2][288];
    const int wlocal = threadIdx.x >> 5;
    const int lane   = threadIdx.x & 31;
    const int cg     = lane >> 2;
    const int mg     = lane & 3;

    // Per-warp constants (loaded once): wp[f][cp] = (w[8cg+2cp][f], w[8cg+2cp+1][f])
    unsigned long long wp[9][4];
    #pragma unroll
    for (int cp = 0; cp < 4; cp++) {
        const float* w0 = cw + (cg * 8 + 2 * cp) * 9;
        #pragma unroll
        for (int f = 0; f < 9; f++)
            wp[f][cp] = pack2(w0[f], w0[9 + f]);
    }
    const int cs = cg * 8 + mg * 2;   // channels this lane stores
    const float s0 = gamma[cs]     * rsqrtf(var[cs]     + 1e-5f);
    const float s1 = gamma[cs + 1] * rsqrtf(var[cs + 1] + 1e-5f);
    const float b0 = beta[cs]     - mean[cs]     * s0;
    const float b1 = beta[cs + 1] - mean[cs + 1] * s1;

    const int count = g_count;
    const int w0id  = (blockIdx.x * blockDim.x + threadIdx.x) >> 5;
    int i = w0id;
    if (i >= count) return;

    // Stage pillar i into registers (9 floats/lane, coalesced: lane+32k)
    int2 eA = g_list[i];
    float xv[9];
    {
        const float* src = pillars + (size_t)eA.x * 288;
        #pragma unroll
        for (int k = 0; k < 9; k++) xv[k] = src[lane + 32 * k];
    }
    int pb = 0;

    for (; i < count; i += NWARPS) {
        // Write current pillar, duplicated, into smem buffer pb
        float2* buf = sm[wlocal][pb];
        #pragma unroll
        for (int k = 0; k < 9; k++)
            buf[lane + 32 * k] = make_float2(xv[k], xv[k]);
        __syncwarp();

        // Prefetch next list entry + pillar into registers
        const int inext = i + NWARPS;
        int2 eB = g_list[(inext < count) ? inext : i];
        if (inext < count) {
            const float* src = pillars + (size_t)eB.x * 288;
            #pragma unroll
            for (int k = 0; k < 9; k++) xv[k] = src[lane + 32 * k];
        }

        // Compute: 8 channel maxes over this lane's 8 m-points
        float mx[8];
        #pragma unroll
        for (int j = 0; j < 8; j++) mx[j] = -3.402823466e38f;

        #pragma unroll
        for (int mi = 0; mi < 8; mi++) {
            const unsigned long long* xr =
                reinterpret_cast<const unsigned long long*>(buf + (mg * 8 + mi) * 9);
            unsigned long long a0 = 0ull, a1 = 0ull, a2 = 0ull, a3 = 0ull;
            #pragma unroll
            for (int f = 0; f < 9; f++) {
                const unsigned long long xs = xr[f];   // LDS.64: (x, x)
                a0 = fma2(xs, wp[f][0], a0);
                a1 = fma2(xs, wp[f][1], a1);
                a2 = fma2(xs, wp[f][2], a2);
                a3 = fma2(xs, wp[f][3], a3);
            }
            float t0, t1;
            unpack2(a0, t0, t1); mx[0] = fmaxf(mx[0], t0); mx[1] = fmaxf(mx[1], t1);
            unpack2(a1, t0, t1); mx[2] = fmaxf(mx[2], t0); mx[3] = fmaxf(mx[3], t1);
            unpack2(a2, t0, t1); mx[4] = fmaxf(mx[4], t0); mx[5] = fmaxf(mx[5], t1);
            unpack2(a3, t0, t1); mx[6] = fmaxf(mx[6], t0); mx[7] = fmaxf(mx[7], t1);
        }

        // Reduce max over the 4 mg lanes (lane = cg*4 + mg)
        #pragma unroll
        for (int j = 0; j < 8; j++) {
            mx[j] = fmaxf(mx[j], __shfl_xor_sync(0xFFFFFFFFu, mx[j], 1));
            mx[j] = fmaxf(mx[j], __shfl_xor_sync(0xFFFFFFFFu, mx[j], 2));
        }

        // BN+ReLU applied once to the raw max (scale>0, monotone => exact)
        const float fA = fmaxf(fmaf(mx[mg * 2],     s0, b0), 0.0f);
        const float fB = fmaxf(fmaf(mx[mg * 2 + 1], s1, b1), 0.0f);
        // Dense channel-major store: warp covers 64 consecutive floats
        reinterpret_cast<float2*>(g_feat + ((size_t)eA.y << 6))[lane] =
            make_float2(fA, fB);

        eA = eB;
        pb ^= 1;
    }
}

// Transpose g_feat [b][cell][c] -> out [b][c][cell], writing zeros for empty
// cells (also replaces the output memset). Tile = 32 cells x 64 channels.
__global__ void __launch_bounds__(256) k_transpose(float* __restrict__ out) {
    __shared__ float ts[64][33];
    __shared__ int win[32];
    const int t     = threadIdx.x;
    const int b     = blockIdx.y;
    const int cell0 = blockIdx.x * 32;

    if (t < 32) win[t] = g_winner[b * CELLS + cell0 + t];
    __syncthreads();

    {
        const int c = t & 63;
        #pragma unroll
        for (int k = 0; k < 8; k++) {
            const int cl = (t >> 6) + k * 4;
            float v = 0.0f;
            if (win[cl] >= 0)
                v = g_feat[(((size_t)(b * CELLS + cell0 + cl)) << 6) + c];
            ts[c][cl] = v;
        }
    }
    __syncthreads();
    {
        const int cl = t & 31;
        #pragma unroll
        for (int k = 0; k < 8; k++) {
            const int c = (t >> 5) + k * 8;
            out[((size_t)(b * 64 + c)) * CELLS + cell0 + cl] = ts[c][cl];
        }
    }
}

extern "C" void kernel_launch(void* const* d_in, const int* in_sizes, int n_in,
                              void* d_out, int out_size) {
    const float* pillars = (const float*)d_in[0];
    const int*   idx     = (const int*)d_in[1];
    const float* cw      = (const float*)d_in[2];
    const float* gamma   = (const float*)d_in[3];
    const float* beta    = (const float*)d_in[4];
    const float* mean    = (const float*)d_in[5];
    const float* var     = (const float*)d_in[6];
    float* out = (float*)d_out;

    void *winner_ptr = nullptr, *count_ptr = nullptr;
    cudaGetSymbolAddress(&winner_ptr, g_winner);
    cudaGetSymbolAddress(&count_ptr, g_count);

    cudaMemsetAsync(winner_ptr, 0xFF, sizeof(int) * NC, 0);  // -1
    cudaMemsetAsync(count_ptr, 0, sizeof(int), 0);
    k_winner<<<NP / 256, 256>>>(idx);
    k_collect<<<NP / 256, 256>>>(idx);
    k_compute<<<NBLK, 256>>>(pillars, cw, gamma, beta, mean, var);
    k_transpose<<<dim3(CELLS / 32, BB), 256>>>(out);
}

// round 14
// speedup vs baseline: 1.1452x; 1.1452x over previous
#include <cuda_runtime.h>

#define BB 8
#define PP 12000
#define NP (BB*PP)
#define XN_ 144
#define CELLS (144*144)
#define NC (BB*CELLS)
#define NBLK 304
#define NWARPS (NBLK*8)

// per-(batch,cell) winning pillar index (last write wins == max p)
__device__ int  g_winner[NC];
__device__ int  g_count;
__device__ int2 g_list[NP];      // (pillar id, out-base = b*64*CELLS + flat)

__global__ void k_winner(const int* __restrict__ idx) {
    int i = blockIdx.x * blockDim.x + threadIdx.x;   // grid sized exactly NP
    int y = idx[i * 3 + 1];
    int x = idx[i * 3 + 2];
    x = min(max(x, 0), 143);
    y = min(max(y, 0), 143);
    int b = i / PP;
    int p = i - b * PP;
    atomicMax(&g_winner[b * CELLS + y * XN_ + x], p);
}

// Compact winners into g_list (warp-aggregated atomic: 1 atomicAdd per warp).
__global__ void k_collect(const int* __restrict__ idx) {
    int i = blockIdx.x * blockDim.x + threadIdx.x;
    int lane = threadIdx.x & 31;
    int y = idx[i * 3 + 1];
    int x = idx[i * 3 + 2];
    x = min(max(x, 0), 143);
    y = min(max(y, 0), 143);
    int b = i / PP;
    int p = i - b * PP;
    int flat = y * XN_ + x;
    bool win = (g_winner[b * CELLS + flat] == p);
    unsigned m = __ballot_sync(0xFFFFFFFFu, win);
    int base = 0;
    if (lane == 0 && m) base = atomicAdd(&g_count, __popc(m));
    base = __shfl_sync(0xFFFFFFFFu, base, 0);
    if (win) {
        int pos = base + __popc(m & ((1u << lane) - 1u));
        g_list[pos] = make_int2(i, b * 64 * CELLS + flat);
    }
}

__device__ __forceinline__ unsigned long long fma2(unsigned long long a,
                                                   unsigned long long b,
                                                   unsigned long long c) {
    unsigned long long d;
    asm("fma.rn.f32x2 %0, %1, %2, %3;" : "=l"(d) : "l"(a), "l"(b), "l"(c));
    return d;
}
__device__ __forceinline__ unsigned long long splat2(float s) {
    unsigned long long d;
    asm("mov.b64 %0, {%1, %1};" : "=l"(d) : "f"(s));
    return d;
}
__device__ __forceinline__ unsigned long long pack2(float lo, float hi) {
    unsigned long long d;
    asm("mov.b64 %0, {%1, %2};" : "=l"(d) : "f"(lo), "f"(hi));
    return d;
}
__device__ __forceinline__ void unpack2(unsigned long long v, float& lo, float& hi) {
    asm("mov.b64 {%0, %1}, %2;" : "=f"(lo), "=f"(hi) : "l"(v));
}
__device__ __forceinline__ unsigned smaddr(const void* p) {
    unsigned r;
    asm("{ .reg .u64 t; cvta.to.shared.u64 t, %1; cvt.u32.u64 %0, t; }"
        : "=r"(r) : "l"(p));
    return r;
}
// Copy one 1152-byte pillar global->shared via cp.async (72 x 16B chunks).
__device__ __forceinline__ void cp_pillar(unsigned sbase, const float* g, int lane) {
    asm volatile("cp.async.cg.shared.global [%0], [%1], 16;"
                 :: "r"(sbase + lane * 16), "l"(g + lane * 4));
    asm volatile("cp.async.cg.shared.global [%0], [%1], 16;"
                 :: "r"(sbase + (lane + 32) * 16), "l"(g + (lane + 32) * 4));
    if (lane < 8)
        asm volatile("cp.async.cg.shared.global [%0], [%1], 16;"
                     :: "r"(sbase + (lane + 64) * 16), "l"(g + (lane + 64) * 4));
}

// Persistent kernel over the compacted winner list. TWO pillars per warp per
// iteration (list positions i and i+NWARPS) sharing the register-resident
// weights: 8 independent FFMA2 accumulator chains + 2 LDS streams per warp
// -> double the per-warp ILP that was pinning issue at ~45%.
// Lane = (cg, mg): cg = lane>>2 owns channels [8cg, 8cg+8),
//                  mg = lane&3  owns m-points  [8mg, 8mg+8).
// 4 smem buffers per warp; pair k+1 prefetched via cp.async during pair k.
__global__ void __launch_bounds__(256, 2) k_compute(
    const float* __restrict__ pillars,
    const float* __restrict__ cw,
    const float* __restrict__ gamma,
    const float* __restrict__ beta,
    const float* __restrict__ mean,
    const float* __restrict__ var,
    float* __restrict__ out)
{
    __shared__ __align__(16) float sm[8][4][288];
    const int wlocal = threadIdx.x >> 5;
    const int lane   = threadIdx.x & 31;
    const int cg     = lane >> 2;
    const int mg     = lane & 3;

    // Per-warp constants (loaded once): wp[f][cp] = (w[8cg+2cp][f], w[8cg+2cp+1][f])
    unsigned long long wp[9][4];
    #pragma unroll
    for (int cp = 0; cp < 4; cp++) {
        const float* w0 = cw + (cg * 8 + 2 * cp) * 9;
        #pragma unroll
        for (int f = 0; f < 9; f++)
            wp[f][cp] = pack2(w0[f], w0[9 + f]);
    }
    const int cs = cg * 8 + mg * 2;   // channels this lane stores
    const float s0 = gamma[cs]     * rsqrtf(var[cs]     + 1e-5f);
    const float s1 = gamma[cs + 1] * rsqrtf(var[cs + 1] + 1e-5f);
    const float b0 = beta[cs]     - mean[cs]     * s0;
    const float b1 = beta[cs + 1] - mean[cs + 1] * s1;

    const int count = g_count;
    const int w0id  = (blockIdx.x * blockDim.x + threadIdx.x) >> 5;
    int i = w0id;
    if (i >= count) return;

    unsigned sb0 = smaddr(&sm[wlocal][0][0]);
    unsigned sb1 = smaddr(&sm[wlocal][1][0]);
    unsigned sb2 = smaddr(&sm[wlocal][2][0]);
    unsigned sb3 = smaddr(&sm[wlocal][3][0]);

    // Prologue: stage pair (i, i+NWARPS)
    int2 cA = g_list[i];
    int  j1 = i + NWARPS;
    int2 cB = g_list[(j1 < count) ? j1 : i];
    cp_pillar(sb0, pillars + (size_t)cA.x * 288, lane);
    if (j1 < count)
        cp_pillar(sb1, pillars + (size_t)cB.x * 288, lane);
    asm volatile("cp.async.commit_group;");
    int pb = 0;   // current pair lives in buffers {pb, pb|1}; pb in {0, 2}

    for (; i < count; i += 2 * NWARPS) {
        __syncwarp();   // nobody still reading the buffers we are about to fill

        // Prefetch next pair into the other buffer set
        const int ni  = i + 2 * NWARPS;
        const int ni1 = ni + NWARPS;
        int2 nA = g_list[(ni  < count) ? ni  : i];
        int2 nB = g_list[(ni1 < count) ? ni1 : i];
        if (ni < count)
            cp_pillar(pb ? sb0 : sb2, pillars + (size_t)nA.x * 288, lane);
        if (ni1 < count)
            cp_pillar(pb ? sb1 : sb3, pillars + (size_t)nB.x * 288, lane);
        asm volatile("cp.async.commit_group;");
        asm volatile("cp.async.wait_group 1;");   // current pair ready
        __syncwarp();

        const float* bufA = &sm[wlocal][pb][0];
        const float* bufB = &sm[wlocal][pb | 1][0];

        float mxA[8], mxB[8];
        #pragma unroll
        for (int j = 0; j < 8; j++) { mxA[j] = -3.402823466e38f; mxB[j] = -3.402823466e38f; }

        #pragma unroll
        for (int mi = 0; mi < 8; mi++) {
            const float* xrA = bufA + (mg * 8 + mi) * 9;
            const float* xrB = bufB + (mg * 8 + mi) * 9;
            unsigned long long a0 = 0ull, a1 = 0ull, a2 = 0ull, a3 = 0ull;
            unsigned long long q0 = 0ull, q1 = 0ull, q2 = 0ull, q3 = 0ull;
            #pragma unroll
            for (int f = 0; f < 9; f++) {
                const unsigned long long xa = splat2(xrA[f]);
                a0 = fma2(xa, wp[f][0], a0);
                a1 = fma2(xa, wp[f][1], a1);
                a2 = fma2(xa, wp[f][2], a2);
                a3 = fma2(xa, wp[f][3], a3);
                const unsigned long long xb = splat2(xrB[f]);
                q0 = fma2(xb, wp[f][0], q0);
                q1 = fma2(xb, wp[f][1], q1);
                q2 = fma2(xb, wp[f][2], q2);
                q3 = fma2(xb, wp[f][3], q3);
            }
            float t0, t1;
            unpack2(a0, t0, t1); mxA[0] = fmaxf(mxA[0], t0); mxA[1] = fmaxf(mxA[1], t1);
            unpack2(a1, t0, t1); mxA[2] = fmaxf(mxA[2], t0); mxA[3] = fmaxf(mxA[3], t1);
            unpack2(a2, t0, t1); mxA[4] = fmaxf(mxA[4], t0); mxA[5] = fmaxf(mxA[5], t1);
            unpack2(a3, t0, t1); mxA[6] = fmaxf(mxA[6], t0); mxA[7] = fmaxf(mxA[7], t1);
            unpack2(q0, t0, t1); mxB[0] = fmaxf(mxB[0], t0); mxB[1] = fmaxf(mxB[1], t1);
            unpack2(q1, t0, t1); mxB[2] = fmaxf(mxB[2], t0); mxB[3] = fmaxf(mxB[3], t1);
            unpack2(q2, t0, t1); mxB[4] = fmaxf(mxB[4], t0); mxB[5] = fmaxf(mxB[5], t1);
            unpack2(q3, t0, t1); mxB[6] = fmaxf(mxB[6], t0); mxB[7] = fmaxf(mxB[7], t1);
        }

        // Reduce max over the 4 mg lanes (lane = cg*4 + mg)
        #pragma unroll
        for (int j = 0; j < 8; j++) {
            mxA[j] = fmaxf(mxA[j], __shfl_xor_sync(0xFFFFFFFFu, mxA[j], 1));
            mxA[j] = fmaxf(mxA[j], __shfl_xor_sync(0xFFFFFFFFu, mxA[j], 2));
            mxB[j] = fmaxf(mxB[j], __shfl_xor_sync(0xFFFFFFFFu, mxB[j], 1));
            mxB[j] = fmaxf(mxB[j], __shfl_xor_sync(0xFFFFFFFFu, mxB[j], 2));
        }

        // BN+ReLU once on the raw max (scale>0, monotone => exact)
        {
            const float fA = fmaxf(fmaf(mxA[mg * 2],     s0, b0), 0.0f);
            const float fB = fmaxf(fmaf(mxA[mg * 2 + 1], s1, b1), 0.0f);
            const size_t base = (size_t)cA.y + (size_t)cs * CELLS;
            out[base]         = fA;
            out[base + CELLS] = fB;
        }
        if (i + NWARPS < count) {
            const float fA = fmaxf(fmaf(mxB[mg * 2],     s0, b0), 0.0f);
            const float fB = fmaxf(fmaf(mxB[mg * 2 + 1], s1, b1), 0.0f);
            const size_t base = (size_t)cB.y + (size_t)cs * CELLS;
            out[base]         = fA;
            out[base + CELLS] = fB;
        }

        cA = nA; cB = nB;
        pb ^= 2;
    }
}

extern "C" void kernel_launch(void* const* d_in, const int* in_sizes, int n_in,
                              void* d_out, int out_size) {
    const float* pillars = (const float*)d_in[0];
    const int*   idx     = (const int*)d_in[1];
    const float* cw      = (const float*)d_in[2];
    const float* gamma   = (const float*)d_in[3];
    const float* beta    = (const float*)d_in[4];
    const float* mean    = (const float*)d_in[5];
    const float* var     = (const float*)d_in[6];
    float* out = (float*)d_out;

    void *winner_ptr = nullptr, *count_ptr = nullptr;
    cudaGetSymbolAddress(&winner_ptr, g_winner);
    cudaGetSymbolAddress(&count_ptr, g_count);

    cudaMemsetAsync(out, 0, (size_t)out_size * sizeof(float), 0);
    cudaMemsetAsync(winner_ptr, 0xFF, sizeof(int) * NC, 0);  // -1
    cudaMemsetAsync(count_ptr, 0, sizeof(int), 0);
    k_winner<<<NP / 256, 256>>>(idx);
    k_collect<<<NP / 256, 256>>>(idx);
    k_compute<<<NBLK, 256>>>(pillars, cw, gamma, beta, mean, var, out);
}